// round 1
// baseline (speedup 1.0000x reference)
#include <cuda_runtime.h>
#include <math.h>

#define Nn 8
#define Cc 256
#define Ll 512
#define Kk 100
#define ROWS (Nn * Ll)          // 4096
#define INV_TEMP 2.0f           // 1/0.5
#define EPS 1e-8f

// Scratch (no runtime allocation allowed)
__device__ float g_zt[ROWS * Cc];   // z transposed to (N*L, C), contiguous rows
__device__ float g_ct[ROWS * Cc];   // c[..., 1:] transposed to (N*L, C)
__device__ float g_invz[ROWS];
__device__ float g_invc[ROWS];

// ---------------------------------------------------------------------------
// Tiled transpose: in (N, C, cols_in) -> g_zt / g_ct as (N*L, C)
// which==0 -> g_zt (col_off 0, cols_in=512); which==1 -> g_ct (col_off 1, 513)
// ---------------------------------------------------------------------------
__global__ void transpose_k(const float* __restrict__ in, int cols_in,
                            int col_off, int which)
{
    __shared__ float tile[32][33];
    float* out = which ? g_ct : g_zt;

    int n  = blockIdx.z;
    int l0 = blockIdx.x * 32;      // output-row tile (l)
    int c0 = blockIdx.y * 32;      // channel tile (c)
    int tx = threadIdx.x, ty = threadIdx.y;

    const float* src = in + (size_t)n * Cc * cols_in;
#pragma unroll
    for (int i = 0; i < 32; i += 8)
        tile[ty + i][tx] = src[(size_t)(c0 + ty + i) * cols_in + col_off + l0 + tx];
    __syncthreads();

    float* dst = out + (size_t)n * Ll * Cc;
#pragma unroll
    for (int i = 0; i < 32; i += 8)
        dst[(size_t)(l0 + ty + i) * Cc + c0 + tx] = tile[tx][ty + i];
}

// ---------------------------------------------------------------------------
// Per-row inverse norms. One warp per row. block=256 (8 warps), grid=512.
// ---------------------------------------------------------------------------
__global__ void norm_k(int which)
{
    const float* m = which ? g_ct : g_zt;
    float* inv     = which ? g_invc : g_invz;

    int row  = blockIdx.x * 8 + (threadIdx.x >> 5);
    int lane = threadIdx.x & 31;

    const float4* r = (const float4*)(m + (size_t)row * Cc);
    float4 a = r[lane];
    float4 b = r[32 + lane];
    float s = a.x * a.x + a.y * a.y + a.z * a.z + a.w * a.w
            + b.x * b.x + b.y * b.y + b.z * b.z + b.w * b.w;
#pragma unroll
    for (int off = 16; off; off >>= 1)
        s += __shfl_xor_sync(0xffffffffu, s, off);
    if (lane == 0)
        inv[row] = 1.0f / fmaxf(sqrtf(s), EPS);
}

// ---------------------------------------------------------------------------
// Main: one block per row (4096 blocks, 128 threads = 4 warps).
// Each warp computes 25-26 of the 101 dot products (d==100 is the positive).
// Then warp 0 does the row logsumexp and atomically accumulates the mean.
// ---------------------------------------------------------------------------
__global__ void logits_k(const int* __restrict__ neg_inds, float* __restrict__ out)
{
    __shared__ float c_sh[Cc];
    __shared__ float logit_sh[Kk + 1];

    int row  = blockIdx.x;
    int tid  = threadIdx.x;
    int warp = tid >> 5;
    int lane = tid & 31;

    // stage c row into shared, then into registers (2x float4 per lane)
    ((float2*)c_sh)[tid] = ((const float2*)(g_ct + (size_t)row * Cc))[tid];
    __syncthreads();

    float4 ca = ((const float4*)c_sh)[lane];
    float4 cb = ((const float4*)c_sh)[32 + lane];
    float invc = g_invc[row];
    const int* inds = neg_inds + (size_t)row * Kk;

    for (int d = warp; d < Kk + 1; d += 4) {
        int j = (d == Kk) ? row : __ldg(&inds[d]);
        const float4* zr = (const float4*)(g_zt + (size_t)j * Cc);
        float4 za = zr[lane];
        float4 zb = zr[32 + lane];
        float s = ca.x * za.x + ca.y * za.y + ca.z * za.z + ca.w * za.w
                + cb.x * zb.x + cb.y * zb.y + cb.z * zb.z + cb.w * zb.w;
#pragma unroll
        for (int off = 16; off; off >>= 1)
            s += __shfl_xor_sync(0xffffffffu, s, off);
        if (lane == 0) {
            float logit = s * invc * g_invz[j] * INV_TEMP;
            logit_sh[(d == Kk) ? 0 : d + 1] = logit;
        }
    }
    __syncthreads();

    if (warp == 0) {
        float v0 = logit_sh[lane];
        float v1 = (lane + 32 < Kk + 1) ? logit_sh[lane + 32] : -INFINITY;
        float v2 = (lane + 64 < Kk + 1) ? logit_sh[lane + 64] : -INFINITY;
        float v3 = (lane + 96 < Kk + 1) ? logit_sh[lane + 96] : -INFINITY;
        float m = fmaxf(fmaxf(v0, v1), fmaxf(v2, v3));
#pragma unroll
        for (int off = 16; off; off >>= 1)
            m = fmaxf(m, __shfl_xor_sync(0xffffffffu, m, off));
        float e = __expf(v0 - m)
                + ((lane + 32 < Kk + 1) ? __expf(v1 - m) : 0.0f)
                + ((lane + 64 < Kk + 1) ? __expf(v2 - m) : 0.0f)
                + ((lane + 96 < Kk + 1) ? __expf(v3 - m) : 0.0f);
#pragma unroll
        for (int off = 16; off; off >>= 1)
            e += __shfl_xor_sync(0xffffffffu, e, off);
        if (lane == 0) {
            float item = m + logf(e) - logit_sh[0];
            atomicAdd(out, item * (1.0f / (float)ROWS));
        }
    }
}

extern "C" void kernel_launch(void* const* d_in, const int* in_sizes, int n_in,
                              void* d_out, int out_size)
{
    const float* z  = (const float*)d_in[0];   // (8, 256, 512)
    const float* c  = (const float*)d_in[1];   // (8, 256, 513)
    const int* inds = (const int*)d_in[2];     // (8, 512, 100)
    float* out = (float*)d_out;

    dim3 tb(32, 8);
    dim3 tg(Ll / 32, Cc / 32, Nn);             // (16, 8, 8)
    transpose_k<<<tg, tb>>>(z, Ll, 0, 0);
    transpose_k<<<tg, tb>>>(c, Ll + 1, 1, 1);

    norm_k<<<ROWS / 8, 256>>>(0);
    norm_k<<<ROWS / 8, 256>>>(1);

    cudaMemsetAsync(d_out, 0, sizeof(float));
    logits_k<<<ROWS, 128>>>(inds, out);
}

// round 2
// speedup vs baseline: 1.0050x; 1.0050x over previous
#include <cuda_runtime.h>
#include <cuda_bf16.h>
#include <math.h>

#define Nn 8
#define Cc 256
#define Ll 512
#define Kk 100
#define ROWS (Nn * Ll)          // 4096
#define CTILES (Cc / 32)        // 8
#define INV_TEMP 2.0f           // 1/0.5
#define EPS 1e-8f

// Scratch (no runtime allocation allowed)
__device__ __nv_bfloat16 g_zt[ROWS * Cc];  // z transposed, bf16 (halves gather bytes)
__device__ float g_ct[ROWS * Cc];          // c[..., 1:] transposed, fp32
__device__ float g_pz[ROWS * CTILES];      // per-(row, c-tile) partial sum-of-squares
__device__ float g_pc[ROWS * CTILES];
__device__ float g_invz[ROWS];
__device__ float g_invc[ROWS];

// ---------------------------------------------------------------------------
// Fused transpose + partial sum-of-squares.
// in (N, C, cols_in) -> (N*L, C). which==0: z -> bf16 g_zt; which==1: c -> g_ct.
// Each block owns one (l-tile, c-tile); partials go to a block-unique slot.
// ---------------------------------------------------------------------------
__global__ void fuse_k(const float* __restrict__ in, int cols_in,
                       int col_off, int which)
{
    __shared__ float tile[32][33];

    int n  = blockIdx.z;
    int l0 = blockIdx.x * 32;      // output-row tile (l)
    int c0 = blockIdx.y * 32;      // channel tile (c)
    int tx = threadIdx.x, ty = threadIdx.y;

    const float* src = in + (size_t)n * Cc * cols_in;
#pragma unroll
    for (int i = 0; i < 32; i += 8)
        tile[ty + i][tx] = src[(size_t)(c0 + ty + i) * cols_in + col_off + l0 + tx];
    __syncthreads();

    size_t rbase = (size_t)n * Ll + l0;
#pragma unroll
    for (int i = 0; i < 32; i += 8) {
        int row = (int)rbase + ty + i;
        float v = tile[tx][ty + i];
        if (which)
            g_ct[(size_t)row * Cc + c0 + tx] = v;
        else
            g_zt[(size_t)row * Cc + c0 + tx] = __float2bfloat16(v);
        // warp-wide (x spans one warp) reduction of v^2 for this output row
        float s = v * v;
#pragma unroll
        for (int off = 16; off; off >>= 1)
            s += __shfl_xor_sync(0xffffffffu, s, off);
        if (tx == 0)
            (which ? g_pc : g_pz)[(size_t)row * CTILES + blockIdx.y] = s;
    }
}

// ---------------------------------------------------------------------------
// Finalize inverse norms: one thread per row, sums 8 partials for z and c.
// ---------------------------------------------------------------------------
__global__ void finalize_k()
{
    int row = blockIdx.x * blockDim.x + threadIdx.x;
    if (row >= ROWS) return;
    float sz = 0.f, sc = 0.f;
#pragma unroll
    for (int t = 0; t < CTILES; t++) {
        sz += g_pz[(size_t)row * CTILES + t];
        sc += g_pc[(size_t)row * CTILES + t];
    }
    g_invz[row] = 1.0f / fmaxf(sqrtf(sz), EPS);
    g_invc[row] = 1.0f / fmaxf(sqrtf(sc), EPS);
}

// ---------------------------------------------------------------------------
// Main: one block per row (4096 blocks, 128 threads = 4 warps).
// Each warp computes 25-26 of the 101 dots (d==100 is the positive).
// z rows are bf16 (512 B gather/dot); c row cached fp32 in registers.
// ---------------------------------------------------------------------------
__global__ void logits_k(const int* __restrict__ neg_inds, float* __restrict__ out)
{
    __shared__ float c_sh[Cc];
    __shared__ float logit_sh[Kk + 1];

    int row  = blockIdx.x;
    int tid  = threadIdx.x;
    int warp = tid >> 5;
    int lane = tid & 31;

    ((float2*)c_sh)[tid] = ((const float2*)(g_ct + (size_t)row * Cc))[tid];
    __syncthreads();

    float cr[8];
#pragma unroll
    for (int t = 0; t < 8; t++)
        cr[t] = c_sh[8 * lane + t];
    float invc = g_invc[row];
    const int* inds = neg_inds + (size_t)row * Kk;

    for (int d = warp; d < Kk + 1; d += 4) {
        int j = (d == Kk) ? row : __ldg(&inds[d]);
        // lane reads 16 B = 8 bf16 elements [8*lane, 8*lane+8)
        uint4 p = ((const uint4*)(g_zt + (size_t)j * Cc))[lane];
        float2 f0 = __bfloat1622float2(*reinterpret_cast<const __nv_bfloat162*>(&p.x));
        float2 f1 = __bfloat1622float2(*reinterpret_cast<const __nv_bfloat162*>(&p.y));
        float2 f2 = __bfloat1622float2(*reinterpret_cast<const __nv_bfloat162*>(&p.z));
        float2 f3 = __bfloat1622float2(*reinterpret_cast<const __nv_bfloat162*>(&p.w));
        float s = cr[0] * f0.x + cr[1] * f0.y
                + cr[2] * f1.x + cr[3] * f1.y
                + cr[4] * f2.x + cr[5] * f2.y
                + cr[6] * f3.x + cr[7] * f3.y;
#pragma unroll
        for (int off = 16; off; off >>= 1)
            s += __shfl_xor_sync(0xffffffffu, s, off);
        if (lane == 0) {
            float logit = s * invc * g_invz[j] * INV_TEMP;
            logit_sh[(d == Kk) ? 0 : d + 1] = logit;
        }
    }
    __syncthreads();

    if (warp == 0) {
        float v0 = logit_sh[lane];
        float v1 = (lane + 32 < Kk + 1) ? logit_sh[lane + 32] : -INFINITY;
        float v2 = (lane + 64 < Kk + 1) ? logit_sh[lane + 64] : -INFINITY;
        float v3 = (lane + 96 < Kk + 1) ? logit_sh[lane + 96] : -INFINITY;
        float m = fmaxf(fmaxf(v0, v1), fmaxf(v2, v3));
#pragma unroll
        for (int off = 16; off; off >>= 1)
            m = fmaxf(m, __shfl_xor_sync(0xffffffffu, m, off));
        float e = __expf(v0 - m)
                + ((lane + 32 < Kk + 1) ? __expf(v1 - m) : 0.0f)
                + ((lane + 64 < Kk + 1) ? __expf(v2 - m) : 0.0f)
                + ((lane + 96 < Kk + 1) ? __expf(v3 - m) : 0.0f);
#pragma unroll
        for (int off = 16; off; off >>= 1)
            e += __shfl_xor_sync(0xffffffffu, e, off);
        if (lane == 0) {
            float item = m + logf(e) - logit_sh[0];
            atomicAdd(out, item * (1.0f / (float)ROWS));
        }
    }
}

extern "C" void kernel_launch(void* const* d_in, const int* in_sizes, int n_in,
                              void* d_out, int out_size)
{
    const float* z  = (const float*)d_in[0];   // (8, 256, 512)
    const float* c  = (const float*)d_in[1];   // (8, 256, 513)
    const int* inds = (const int*)d_in[2];     // (8, 512, 100)
    float* out = (float*)d_out;

    dim3 tb(32, 8);
    dim3 tg(Ll / 32, Cc / 32, Nn);             // (16, 8, 8)
    fuse_k<<<tg, tb>>>(z, Ll, 0, 0);
    fuse_k<<<tg, tb>>>(c, Ll + 1, 1, 1);

    finalize_k<<<(ROWS + 255) / 256, 256>>>();

    cudaMemsetAsync(d_out, 0, sizeof(float));
    logits_k<<<ROWS, 128>>>(inds, out);
}

// round 3
// speedup vs baseline: 1.0100x; 1.0050x over previous
#include <cuda_runtime.h>
#include <cuda_bf16.h>
#include <math.h>

#define Nn 8
#define Cc 256
#define Ll 512
#define Kk 100
#define ROWS (Nn * Ll)          // 4096
#define INV_TEMP 2.0f           // 1/0.5
#define EPS 1e-8f

// Scratch (no runtime allocation allowed)
__device__ float g_zf[ROWS * Cc];          // z transposed, fp32 (pre-scale staging)
__device__ float g_ct[ROWS * Cc];          // c[..., 1:] transposed, fp32
__device__ __nv_bfloat16 g_zt[ROWS * Cc];  // z transposed, NORMALIZED, bf16
__device__ float g_inv[2 * ROWS];          // [0..ROWS): invz, [ROWS..): invc

// ---------------------------------------------------------------------------
// Tiled transpose: in (N, C, cols_in) -> (N*L, C) fp32.
// which==0 -> g_zf (cols_in=512, off 0); which==1 -> g_ct (513, off 1)
// ---------------------------------------------------------------------------
__global__ void transpose_k(const float* __restrict__ in, int cols_in,
                            int col_off, int which)
{
    __shared__ float tile[32][33];
    float* out = which ? g_ct : g_zf;

    int n  = blockIdx.z;
    int l0 = blockIdx.x * 32;
    int c0 = blockIdx.y * 32;
    int tx = threadIdx.x, ty = threadIdx.y;

    const float* src = in + (size_t)n * Cc * cols_in;
#pragma unroll
    for (int i = 0; i < 32; i += 8)
        tile[ty + i][tx] = src[(size_t)(c0 + ty + i) * cols_in + col_off + l0 + tx];
    __syncthreads();

    float* dst = out + (size_t)n * Ll * Cc;
#pragma unroll
    for (int i = 0; i < 32; i += 8)
        dst[(size_t)(l0 + ty + i) * Cc + c0 + tx] = tile[tx][ty + i];
}

// ---------------------------------------------------------------------------
// Inverse norms for both matrices. One warp = 4 rows, loads batched for MLP=8.
// Row r < ROWS -> g_zf; else g_ct row (r - ROWS). grid=256, block=256.
// ---------------------------------------------------------------------------
__global__ void norms_k()
{
    int gwarp = (blockIdx.x * blockDim.x + threadIdx.x) >> 5;
    int lane  = threadIdx.x & 31;
    int r0 = gwarp * 4;

    float4 a[4], b[4];
#pragma unroll
    for (int i = 0; i < 4; i++) {
        int r = r0 + i;
        const float* m = (r < ROWS) ? (g_zf + (size_t)r * Cc)
                                    : (g_ct + (size_t)(r - ROWS) * Cc);
        const float4* p = (const float4*)m;
        a[i] = p[lane];
        b[i] = p[32 + lane];
    }
#pragma unroll
    for (int i = 0; i < 4; i++) {
        float s = a[i].x * a[i].x + a[i].y * a[i].y + a[i].z * a[i].z + a[i].w * a[i].w
                + b[i].x * b[i].x + b[i].y * b[i].y + b[i].z * b[i].z + b[i].w * b[i].w;
#pragma unroll
        for (int off = 16; off; off >>= 1)
            s += __shfl_xor_sync(0xffffffffu, s, off);
        if (lane == 0)
            g_inv[r0 + i] = 1.0f / fmaxf(sqrtf(s), EPS);
    }
}

// ---------------------------------------------------------------------------
// Scale z rows by invz and convert to bf16. Thread = 8 elems; warp = 1 row.
// grid=512, block=256.
// ---------------------------------------------------------------------------
__global__ void scale_k()
{
    int t = blockIdx.x * blockDim.x + threadIdx.x;   // 131072 threads
    int row = t >> 5;
    float inv = g_inv[row];
    float4 x = ((const float4*)g_zf)[2 * t];
    float4 y = ((const float4*)g_zf)[2 * t + 1];
    __nv_bfloat162 h0 = __floats2bfloat162_rn(x.x * inv, x.y * inv);
    __nv_bfloat162 h1 = __floats2bfloat162_rn(x.z * inv, x.w * inv);
    __nv_bfloat162 h2 = __floats2bfloat162_rn(y.x * inv, y.y * inv);
    __nv_bfloat162 h3 = __floats2bfloat162_rn(y.z * inv, y.w * inv);
    uint4 o;
    o.x = *(unsigned*)&h0; o.y = *(unsigned*)&h1;
    o.z = *(unsigned*)&h2; o.w = *(unsigned*)&h3;
    ((uint4*)g_zt)[t] = o;
}

// ---------------------------------------------------------------------------
// Main: one block per row, 128 threads = 8 half-warps. Each half-warp owns
// dots d = h, h+8, ... (13 fixed iterations; d==100 is the positive).
// z rows pre-normalized bf16; c pre-scaled by invc/TEMP -> dot IS the logit.
// Packed f32x2 FMA, bit-op bf16 unpack, 4 shuffles per dot.
// ---------------------------------------------------------------------------
__global__ void logits_k(const int* __restrict__ neg_inds, float* __restrict__ out)
{
    __shared__ float2 c_sh[Cc / 2];
    __shared__ float logit_sh[Kk + 1];

    int row = blockIdx.x;
    int tid = threadIdx.x;
    int h   = tid >> 4;        // half-warp id 0..7
    int hl  = tid & 15;        // lane in half-warp

    float invc = g_inv[ROWS + row] * INV_TEMP;
    float2 cv = ((const float2*)(g_ct + (size_t)row * Cc))[tid];
    cv.x *= invc; cv.y *= invc;
    c_sh[tid] = cv;
    __syncthreads();

    // this lane's 8 packed c pairs (elements [16*hl, 16*hl+16))
    unsigned long long cp[8];
#pragma unroll
    for (int t2 = 0; t2 < 8; t2++) {
        float2 f = c_sh[8 * hl + t2];
        asm("mov.b64 %0, {%1, %2};" : "=l"(cp[t2]) : "f"(f.x), "f"(f.y));
    }

    const int* inds = neg_inds + (size_t)row * Kk;

#pragma unroll 1
    for (int it = 0; it < 13; it++) {
        int d = h + it * 8;
        bool act = (d <= Kk);
        int j = row;
        if (act && d < Kk) j = __ldg(&inds[d]);

        const uint4* zr = (const uint4*)(g_zt + (size_t)j * Cc);
        uint4 p0 = zr[2 * hl];
        uint4 p1 = zr[2 * hl + 1];

        unsigned long long acc0 = 0ull, acc1 = 0ull;
#define STEP(u, k, acc) do {                                                   \
        unsigned _lo = (u) << 16;                                              \
        unsigned _hi = (u) & 0xffff0000u;                                      \
        unsigned long long _zp;                                                \
        asm("mov.b64 %0, {%1, %2};" : "=l"(_zp) : "r"(_lo), "r"(_hi));         \
        asm("fma.rn.f32x2 %0, %1, %2, %0;" : "+l"(acc) : "l"(_zp), "l"(cp[k]));\
    } while (0)
        STEP(p0.x, 0, acc0); STEP(p0.y, 1, acc1);
        STEP(p0.z, 2, acc0); STEP(p0.w, 3, acc1);
        STEP(p1.x, 4, acc0); STEP(p1.y, 5, acc1);
        STEP(p1.z, 6, acc0); STEP(p1.w, 7, acc1);
#undef STEP
        unsigned long long accs;
        asm("add.rn.f32x2 %0, %1, %2;" : "=l"(accs) : "l"(acc0), "l"(acc1));
        float slo, shi;
        asm("mov.b64 {%0, %1}, %2;" : "=f"(slo), "=f"(shi) : "l"(accs));
        float s = slo + shi;
#pragma unroll
        for (int off = 8; off; off >>= 1)
            s += __shfl_xor_sync(0xffffffffu, s, off);
        if (act && hl == 0)
            logit_sh[(d == Kk) ? 0 : d + 1] = s;
    }
    __syncthreads();

    if (tid < 32) {
        int lane = tid;
        float v0 = logit_sh[lane];
        float v1 = (lane + 32 < Kk + 1) ? logit_sh[lane + 32] : -INFINITY;
        float v2 = (lane + 64 < Kk + 1) ? logit_sh[lane + 64] : -INFINITY;
        float v3 = (lane + 96 < Kk + 1) ? logit_sh[lane + 96] : -INFINITY;
        float m = fmaxf(fmaxf(v0, v1), fmaxf(v2, v3));
#pragma unroll
        for (int off = 16; off; off >>= 1)
            m = fmaxf(m, __shfl_xor_sync(0xffffffffu, m, off));
        float e = __expf(v0 - m)
                + ((lane + 32 < Kk + 1) ? __expf(v1 - m) : 0.0f)
                + ((lane + 64 < Kk + 1) ? __expf(v2 - m) : 0.0f)
                + ((lane + 96 < Kk + 1) ? __expf(v3 - m) : 0.0f);
#pragma unroll
        for (int off = 16; off; off >>= 1)
            e += __shfl_xor_sync(0xffffffffu, e, off);
        if (lane == 0) {
            float item = m + logf(e) - logit_sh[0];
            atomicAdd(out, item * (1.0f / (float)ROWS));
        }
    }
}

extern "C" void kernel_launch(void* const* d_in, const int* in_sizes, int n_in,
                              void* d_out, int out_size)
{
    const float* z  = (const float*)d_in[0];   // (8, 256, 512)
    const float* c  = (const float*)d_in[1];   // (8, 256, 513)
    const int* inds = (const int*)d_in[2];     // (8, 512, 100)
    float* out = (float*)d_out;

    dim3 tb(32, 8);
    dim3 tg(Ll / 32, Cc / 32, Nn);             // (16, 8, 8)
    transpose_k<<<tg, tb>>>(z, Ll, 0, 0);
    transpose_k<<<tg, tb>>>(c, Ll + 1, 1, 1);

    norms_k<<<256, 256>>>();
    scale_k<<<512, 256>>>();

    cudaMemsetAsync(d_out, 0, sizeof(float));
    logits_k<<<ROWS, 128>>>(inds, out);
}